// round 1
// baseline (speedup 1.0000x reference)
#include <cuda_runtime.h>
#include <cstdint>

// Problem constants (match reference_code)
#define NROWS 100001
#define DIM   64
#define NNZ_E 3200000
#define ND    (NROWS * DIM)          // 6,400,064 floats per segment
#define ND4   (ND / 4)               // 1,600,016 float4 per segment

// ---------------------------------------------------------------------------
// Kernel 1: initialize output buffer.
//   d_out layout: [summed | e0 | e1 | e2], each ND floats.
//   e0 <- emb_weight (copy), e1 <- 0, e2 <- 0.
// ---------------------------------------------------------------------------
__global__ void init_kernel(const float4* __restrict__ emb,
                            float4* __restrict__ out)
{
    int i = blockIdx.x * blockDim.x + threadIdx.x;
    if (i < ND4) {
        float4 z = make_float4(0.f, 0.f, 0.f, 0.f);
        out[ND4 + i]     = emb[i];  // e0
        out[2 * ND4 + i] = z;       // e1
        out[3 * ND4 + i] = z;       // e2
    }
}

// ---------------------------------------------------------------------------
// Kernel 2: COO SpMM, edge-parallel with vectorized global reductions.
//   y[row[e], :] += vals[e] * x[col[e], :]
//   16 threads per edge, one float4 each (D=64 -> 16 x float4).
//   red.global.add.v4.f32 cuts atomic op count 4x vs scalar atomicAdd.
// ---------------------------------------------------------------------------
__global__ void spmm_kernel(const int*   __restrict__ row,
                            const int*   __restrict__ col,
                            const float* __restrict__ vals,
                            const float4* __restrict__ x,
                            float* __restrict__ y)
{
    long long t = (long long)blockIdx.x * blockDim.x + threadIdx.x;
    int e = (int)(t >> 4);
    int j = (int)(t & 15);
    if (e >= NNZ_E) return;

    int   r = __ldg(row + e);
    int   c = __ldg(col + e);
    float v = __ldg(vals + e);

    float4 xv = __ldg(x + (size_t)c * 16 + j);
    float4 p;
    p.x = v * xv.x; p.y = v * xv.y; p.z = v * xv.z; p.w = v * xv.w;

    float* dst = y + (size_t)r * DIM + j * 4;   // 16B aligned
    asm volatile("red.global.add.v4.f32 [%0], {%1, %2, %3, %4};"
                 :: "l"(dst), "f"(p.x), "f"(p.y), "f"(p.z), "f"(p.w)
                 : "memory");
}

// ---------------------------------------------------------------------------
// Kernel 3: summed = e0 + e1 + e2
// ---------------------------------------------------------------------------
__global__ void sum_kernel(float4* __restrict__ out)
{
    int i = blockIdx.x * blockDim.x + threadIdx.x;
    if (i < ND4) {
        float4 a = out[ND4 + i];
        float4 b = out[2 * ND4 + i];
        float4 c = out[3 * ND4 + i];
        float4 s;
        s.x = a.x + b.x + c.x;
        s.y = a.y + b.y + c.y;
        s.z = a.z + b.z + c.z;
        s.w = a.w + b.w + c.w;
        out[i] = s;
    }
}

// ---------------------------------------------------------------------------
// Launch: init -> spmm(e0 -> e1) -> spmm(e1 -> e2) -> sum
// All in default stream (implicit ordering), graph-capturable, no allocs.
// ---------------------------------------------------------------------------
extern "C" void kernel_launch(void* const* d_in, const int* in_sizes, int n_in,
                              void* d_out, int out_size)
{
    const int*   row  = (const int*)d_in[0];
    const int*   col  = (const int*)d_in[1];
    const float* vals = (const float*)d_in[2];
    const float* emb  = (const float*)d_in[3];

    float* out = (float*)d_out;
    float* e0  = out + (size_t)ND;
    float* e1  = out + (size_t)2 * ND;
    float* e2  = out + (size_t)3 * ND;

    const int TPB = 256;

    // init / copy
    {
        int blocks = (ND4 + TPB - 1) / TPB;
        init_kernel<<<blocks, TPB>>>((const float4*)emb, (float4*)out);
    }

    // layer 1: e1 = A @ e0   (e0 == emb)
    {
        long long total = (long long)NNZ_E * 16;
        int blocks = (int)((total + TPB - 1) / TPB);
        spmm_kernel<<<blocks, TPB>>>(row, col, vals, (const float4*)emb, e1);
    }

    // layer 2: e2 = A @ e1
    {
        long long total = (long long)NNZ_E * 16;
        int blocks = (int)((total + TPB - 1) / TPB);
        spmm_kernel<<<blocks, TPB>>>(row, col, vals, (const float4*)e1, e2);
    }

    // summed = e0 + e1 + e2
    {
        int blocks = (ND4 + TPB - 1) / TPB;
        sum_kernel<<<blocks, TPB>>>((float4*)out);
    }
}

// round 2
// speedup vs baseline: 1.6541x; 1.6541x over previous
#include <cuda_runtime.h>
#include <cstdint>

// Problem constants (match reference_code)
#define NROWS 100001
#define DIM   64
#define NNZ_E 3200000
#define ND    (NROWS * DIM)          // floats per segment
#define ND4   (ND / 4)               // float4 per segment
#define SCAN_B 1024
#define NBLK  ((NROWS + SCAN_B - 1) / SCAN_B)   // 98

// ---------------------------------------------------------------------------
// Static device scratch (no allocations allowed in kernel_launch).
// ---------------------------------------------------------------------------
__device__ int  g_counts[NROWS];        // histogram, then scatter cursors
__device__ int  g_rowptr[NROWS + 1];    // CSR row pointers (exclusive scan)
__device__ int  g_partials[NBLK];       // scan block partials
__device__ int2 g_meta[NNZ_E];          // sorted (col, val-bits) pairs, 25.6MB

// ---------------------------------------------------------------------------
// K1: zero histogram + copy emb -> e0 segment of output.
// ---------------------------------------------------------------------------
__global__ void zero_copy_kernel(const float4* __restrict__ emb,
                                 float4* __restrict__ e0)
{
    int i = blockIdx.x * blockDim.x + threadIdx.x;
    if (i < ND4) e0[i] = emb[i];
    if (i < NROWS) g_counts[i] = 0;
    if (i == 0) g_rowptr[NROWS] = NNZ_E;
}

// ---------------------------------------------------------------------------
// K2: histogram of row indices.
// ---------------------------------------------------------------------------
__global__ void hist_kernel(const int* __restrict__ row)
{
    int i = blockIdx.x * blockDim.x + threadIdx.x;
    if (i < NNZ_E) atomicAdd(&g_counts[row[i]], 1);
}

// ---------------------------------------------------------------------------
// K3a: per-block exclusive scan of counts -> rowptr (block-local) + partials.
// ---------------------------------------------------------------------------
__global__ void scan1_kernel()
{
    __shared__ int s[SCAN_B];
    int gid = blockIdx.x * SCAN_B + threadIdx.x;
    int v = (gid < NROWS) ? g_counts[gid] : 0;
    s[threadIdx.x] = v;
    __syncthreads();
    #pragma unroll
    for (int off = 1; off < SCAN_B; off <<= 1) {
        int t = (threadIdx.x >= off) ? s[threadIdx.x - off] : 0;
        __syncthreads();
        s[threadIdx.x] += t;
        __syncthreads();
    }
    if (gid < NROWS) g_rowptr[gid] = s[threadIdx.x] - v;   // exclusive
    if (threadIdx.x == SCAN_B - 1) g_partials[blockIdx.x] = s[threadIdx.x];
}

// K3b: exclusive scan of the 98 partials (single thread; trivial size).
__global__ void scan2_kernel()
{
    if (threadIdx.x == 0 && blockIdx.x == 0) {
        int run = 0;
        for (int b = 0; b < NBLK; b++) {
            int t = g_partials[b];
            g_partials[b] = run;
            run += t;
        }
    }
}

// K3c: add block bases; duplicate rowptr into counts as scatter cursors.
__global__ void scan3_kernel()
{
    int gid = blockIdx.x * SCAN_B + threadIdx.x;
    if (gid < NROWS) {
        int p = g_rowptr[gid] + g_partials[blockIdx.x];
        g_rowptr[gid] = p;
        g_counts[gid] = p;
    }
}

// ---------------------------------------------------------------------------
// K4: scatter edges into CSR order (order within a row irrelevant).
// ---------------------------------------------------------------------------
__global__ void scatter_kernel(const int* __restrict__ row,
                               const int* __restrict__ col,
                               const float* __restrict__ vals)
{
    int e = blockIdx.x * blockDim.x + threadIdx.x;
    if (e < NNZ_E) {
        int r = row[e];
        int pos = atomicAdd(&g_counts[r], 1);
        g_meta[pos] = make_int2(col[e], __float_as_int(vals[e]));
    }
}

// ---------------------------------------------------------------------------
// K5: CSR SpMM, 16 threads per row, register accumulation, single store.
//   y[r,:] = sum_e vals[e] * x[col[e],:]
//   FUSE: additionally summed[r,:] = e0[r,:] + e1[r,:] + y[r,:]
// ---------------------------------------------------------------------------
template <bool FUSE>
__global__ void spmm_csr_kernel(const float4* __restrict__ x,
                                float4* __restrict__ y,
                                const float4* __restrict__ e0,
                                const float4* __restrict__ e1,
                                float4* __restrict__ summed)
{
    int r = blockIdx.x * (blockDim.x >> 4) + (threadIdx.x >> 4);
    int j = threadIdx.x & 15;
    if (r >= NROWS) return;

    int beg = g_rowptr[r];
    int end = g_rowptr[r + 1];

    float4 acc = make_float4(0.f, 0.f, 0.f, 0.f);
    int e = beg;
    // 2-way unroll for MLP (two independent gathers in flight)
    for (; e + 1 < end; e += 2) {
        int2 m0 = g_meta[e];
        int2 m1 = g_meta[e + 1];
        float4 x0 = __ldg(x + (size_t)m0.x * 16 + j);
        float4 x1 = __ldg(x + (size_t)m1.x * 16 + j);
        float v0 = __int_as_float(m0.y);
        float v1 = __int_as_float(m1.y);
        acc.x = fmaf(v0, x0.x, acc.x); acc.y = fmaf(v0, x0.y, acc.y);
        acc.z = fmaf(v0, x0.z, acc.z); acc.w = fmaf(v0, x0.w, acc.w);
        acc.x = fmaf(v1, x1.x, acc.x); acc.y = fmaf(v1, x1.y, acc.y);
        acc.z = fmaf(v1, x1.z, acc.z); acc.w = fmaf(v1, x1.w, acc.w);
    }
    if (e < end) {
        int2 m0 = g_meta[e];
        float4 x0 = __ldg(x + (size_t)m0.x * 16 + j);
        float v0 = __int_as_float(m0.y);
        acc.x = fmaf(v0, x0.x, acc.x); acc.y = fmaf(v0, x0.y, acc.y);
        acc.z = fmaf(v0, x0.z, acc.z); acc.w = fmaf(v0, x0.w, acc.w);
    }

    size_t o = (size_t)r * 16 + j;
    y[o] = acc;
    if (FUSE) {
        float4 a = e0[o];
        float4 b = e1[o];
        float4 s;
        s.x = a.x + b.x + acc.x;
        s.y = a.y + b.y + acc.y;
        s.z = a.z + b.z + acc.z;
        s.w = a.w + b.w + acc.w;
        summed[o] = s;
    }
}

// ---------------------------------------------------------------------------
// Launch sequence (default stream, graph-capturable, no allocations):
//   zero+copy -> hist -> scan(3) -> scatter -> spmm L1 -> spmm L2 (+sum fused)
// ---------------------------------------------------------------------------
extern "C" void kernel_launch(void* const* d_in, const int* in_sizes, int n_in,
                              void* d_out, int out_size)
{
    const int*   row  = (const int*)d_in[0];
    const int*   col  = (const int*)d_in[1];
    const float* vals = (const float*)d_in[2];
    const float* emb  = (const float*)d_in[3];

    float* out = (float*)d_out;
    float4* summed = (float4*)out;
    float4* e0 = (float4*)(out + (size_t)ND);
    float4* e1 = (float4*)(out + (size_t)2 * ND);
    float4* e2 = (float4*)(out + (size_t)3 * ND);

    const int TPB = 256;

    // K1: zero counts + copy e0
    zero_copy_kernel<<<(ND4 + TPB - 1) / TPB, TPB>>>((const float4*)emb, e0);

    // K2: histogram
    hist_kernel<<<(NNZ_E + TPB - 1) / TPB, TPB>>>(row);

    // K3: exclusive scan -> rowptr + cursors
    scan1_kernel<<<NBLK, SCAN_B>>>();
    scan2_kernel<<<1, 32>>>();
    scan3_kernel<<<NBLK, SCAN_B>>>();

    // K4: scatter to CSR
    scatter_kernel<<<(NNZ_E + TPB - 1) / TPB, TPB>>>(row, col, vals);

    // K5: layer 1  e1 = A @ e0
    const int ROWS_PER_BLOCK = TPB / 16;
    int spmm_blocks = (NROWS + ROWS_PER_BLOCK - 1) / ROWS_PER_BLOCK;
    spmm_csr_kernel<false><<<spmm_blocks, TPB>>>((const float4*)e0, e1,
                                                 nullptr, nullptr, nullptr);

    // K6: layer 2  e2 = A @ e1, fused summed = e0 + e1 + e2
    spmm_csr_kernel<true><<<spmm_blocks, TPB>>>((const float4*)e1, e2,
                                                (const float4*)e0,
                                                (const float4*)e1, summed);
}

// round 3
// speedup vs baseline: 1.7665x; 1.0679x over previous
#include <cuda_runtime.h>
#include <cstdint>

// Problem constants (match reference_code)
#define NROWS 100001
#define DIM   64
#define NNZ_E 3200000
#define ND    (NROWS * DIM)          // floats per segment
#define ND4   (ND / 4)               // float4 per segment
#define SCAN_B 1024
#define NBLK  ((NROWS + SCAN_B - 1) / SCAN_B)   // 98

// ---------------------------------------------------------------------------
// Static device scratch (no allocations allowed in kernel_launch).
// ---------------------------------------------------------------------------
__device__ int  g_counts[NROWS];        // histogram, then scatter cursors
__device__ int  g_rowptr[NROWS + 1];    // CSR row pointers (exclusive scan)
__device__ int  g_partials[NBLK];       // scan block partials
__device__ int2 g_meta[NNZ_E];          // CSR-ordered (col, val-bits), 25.6MB

// ---------------------------------------------------------------------------
// K1: zero histogram (tiny).
// ---------------------------------------------------------------------------
__global__ void zero_kernel()
{
    int i = blockIdx.x * blockDim.x + threadIdx.x;
    if (i < NROWS) g_counts[i] = 0;
    if (i == 0) g_rowptr[NROWS] = NNZ_E;
}

// ---------------------------------------------------------------------------
// K2: histogram of row indices, 4 edges/thread via int4 (NNZ_E % 4 == 0).
// ---------------------------------------------------------------------------
__global__ void hist_kernel(const int4* __restrict__ row4)
{
    int i = blockIdx.x * blockDim.x + threadIdx.x;
    if (i < NNZ_E / 4) {
        int4 r = __ldg(row4 + i);
        atomicAdd(&g_counts[r.x], 1);
        atomicAdd(&g_counts[r.y], 1);
        atomicAdd(&g_counts[r.z], 1);
        atomicAdd(&g_counts[r.w], 1);
    }
}

// ---------------------------------------------------------------------------
// K3a: per-block exclusive scan of counts -> rowptr (block-local) + partials.
// ---------------------------------------------------------------------------
__global__ void scan1_kernel()
{
    __shared__ int s[SCAN_B];
    int gid = blockIdx.x * SCAN_B + threadIdx.x;
    int v = (gid < NROWS) ? g_counts[gid] : 0;
    s[threadIdx.x] = v;
    __syncthreads();
    #pragma unroll
    for (int off = 1; off < SCAN_B; off <<= 1) {
        int t = (threadIdx.x >= off) ? s[threadIdx.x - off] : 0;
        __syncthreads();
        s[threadIdx.x] += t;
        __syncthreads();
    }
    if (gid < NROWS) g_rowptr[gid] = s[threadIdx.x] - v;   // exclusive
    if (threadIdx.x == SCAN_B - 1) g_partials[blockIdx.x] = s[threadIdx.x];
}

// K3b: exclusive scan of the 98 partials (one 128-thread block, parallel).
__global__ void scan2_kernel()
{
    __shared__ int s[128];
    int t = threadIdx.x;
    int v = (t < NBLK) ? g_partials[t] : 0;
    s[t] = v;
    __syncthreads();
    #pragma unroll
    for (int off = 1; off < 128; off <<= 1) {
        int u = (t >= off) ? s[t - off] : 0;
        __syncthreads();
        s[t] += u;
        __syncthreads();
    }
    if (t < NBLK) g_partials[t] = s[t] - v;   // exclusive
}

// K3c: add block bases; duplicate rowptr into counts as scatter cursors.
__global__ void scan3_kernel()
{
    int gid = blockIdx.x * SCAN_B + threadIdx.x;
    if (gid < NROWS) {
        int p = g_rowptr[gid] + g_partials[blockIdx.x];
        g_rowptr[gid] = p;
        g_counts[gid] = p;
    }
}

// ---------------------------------------------------------------------------
// K4: scatter edges into CSR order (order within a row irrelevant).
// ---------------------------------------------------------------------------
__global__ void scatter_kernel(const int* __restrict__ row,
                               const int* __restrict__ col,
                               const float* __restrict__ vals)
{
    int e = blockIdx.x * blockDim.x + threadIdx.x;
    if (e < NNZ_E) {
        int r = __ldg(row + e);
        int pos = atomicAdd(&g_counts[r], 1);
        g_meta[pos] = make_int2(__ldg(col + e), __float_as_int(__ldg(vals + e)));
    }
}

// ---------------------------------------------------------------------------
// K5: CSR SpMM, ONE WARP PER ROW, 2 edges concurrently (half-warps),
//     register accumulation, shfl combine, single store.
//   y[r,:] = sum_e vals[e] * x[col[e],:]
//   COPY_E0: also e0[r,:] = x[r,:]           (layer 1, x == emb)
//   FUSE:    also summed[r,:] = e0 + e1 + y  (layer 2)
// ---------------------------------------------------------------------------
template <bool COPY_E0, bool FUSE>
__global__ void spmm_csr_kernel(const float4* __restrict__ x,
                                float4* __restrict__ y,
                                float4* __restrict__ e0_out,
                                const float4* __restrict__ e0,
                                const float4* __restrict__ e1,
                                float4* __restrict__ summed)
{
    int warp = (blockIdx.x * blockDim.x + threadIdx.x) >> 5;
    int lane = threadIdx.x & 31;
    int j    = lane & 15;        // float4 slot within the 64-wide row
    int half = lane >> 4;        // 0 or 1: which edge of the pair
    if (warp >= NROWS) return;
    int r = warp;

    int beg = g_rowptr[r];
    int end = g_rowptr[r + 1];

    float4 acc = make_float4(0.f, 0.f, 0.f, 0.f);
    int e = beg + half;          // half 0: beg, beg+2, ...; half 1: beg+1, beg+3, ...
    // 2-way unroll: edges e and e+2 in flight (4 gathers per warp iteration)
    for (; e + 2 < end; e += 4) {
        int2 m0 = __ldg(&g_meta[e]);
        int2 m1 = __ldg(&g_meta[e + 2]);
        float4 x0 = __ldg(x + (size_t)m0.x * 16 + j);
        float4 x1 = __ldg(x + (size_t)m1.x * 16 + j);
        float v0 = __int_as_float(m0.y);
        float v1 = __int_as_float(m1.y);
        acc.x = fmaf(v0, x0.x, acc.x); acc.y = fmaf(v0, x0.y, acc.y);
        acc.z = fmaf(v0, x0.z, acc.z); acc.w = fmaf(v0, x0.w, acc.w);
        acc.x = fmaf(v1, x1.x, acc.x); acc.y = fmaf(v1, x1.y, acc.y);
        acc.z = fmaf(v1, x1.z, acc.z); acc.w = fmaf(v1, x1.w, acc.w);
    }
    if (e < end) {
        int2 m0 = __ldg(&g_meta[e]);
        float4 x0 = __ldg(x + (size_t)m0.x * 16 + j);
        float v0 = __int_as_float(m0.y);
        acc.x = fmaf(v0, x0.x, acc.x); acc.y = fmaf(v0, x0.y, acc.y);
        acc.z = fmaf(v0, x0.z, acc.z); acc.w = fmaf(v0, x0.w, acc.w);
    }

    // combine the two half-warp partials (lane j gets lane j+16's acc)
    acc.x += __shfl_xor_sync(0xffffffffu, acc.x, 16);
    acc.y += __shfl_xor_sync(0xffffffffu, acc.y, 16);
    acc.z += __shfl_xor_sync(0xffffffffu, acc.z, 16);
    acc.w += __shfl_xor_sync(0xffffffffu, acc.w, 16);

    if (half == 0) {
        size_t o = (size_t)r * 16 + j;
        y[o] = acc;
        if (COPY_E0) {
            e0_out[o] = __ldg(x + o);       // e0 = emb (row-contiguous copy)
        }
        if (FUSE) {
            float4 a = e0[o];
            float4 b = e1[o];
            float4 s;
            s.x = a.x + b.x + acc.x;
            s.y = a.y + b.y + acc.y;
            s.z = a.z + b.z + acc.z;
            s.w = a.w + b.w + acc.w;
            summed[o] = s;
        }
    }
}

// ---------------------------------------------------------------------------
// Launch sequence (default stream, graph-capturable, no allocations):
//   zero -> hist -> scan(3) -> scatter -> spmm L1 (+e0 copy) -> spmm L2 (+sum)
// ---------------------------------------------------------------------------
extern "C" void kernel_launch(void* const* d_in, const int* in_sizes, int n_in,
                              void* d_out, int out_size)
{
    const int*   row  = (const int*)d_in[0];
    const int*   col  = (const int*)d_in[1];
    const float* vals = (const float*)d_in[2];
    const float* emb  = (const float*)d_in[3];

    float* out = (float*)d_out;
    float4* summed = (float4*)out;
    float4* e0 = (float4*)(out + (size_t)ND);
    float4* e1 = (float4*)(out + (size_t)2 * ND);
    float4* e2 = (float4*)(out + (size_t)3 * ND);

    const int TPB = 256;

    // K1: zero counts
    zero_kernel<<<(NROWS + TPB - 1) / TPB, TPB>>>();

    // K2: histogram (4 edges per thread)
    hist_kernel<<<(NNZ_E / 4 + TPB - 1) / TPB, TPB>>>((const int4*)row);

    // K3: exclusive scan -> rowptr + cursors
    scan1_kernel<<<NBLK, SCAN_B>>>();
    scan2_kernel<<<1, 128>>>();
    scan3_kernel<<<NBLK, SCAN_B>>>();

    // K4: scatter to CSR
    scatter_kernel<<<(NNZ_E + TPB - 1) / TPB, TPB>>>(row, col, vals);

    // K5/K6: warp per row
    const int WARPS_PER_BLOCK = TPB / 32;
    int spmm_blocks = (NROWS + WARPS_PER_BLOCK - 1) / WARPS_PER_BLOCK;

    // layer 1: e1 = A @ emb, fused e0 = emb
    spmm_csr_kernel<true, false><<<spmm_blocks, TPB>>>(
        (const float4*)emb, e1, e0, nullptr, nullptr, nullptr);

    // layer 2: e2 = A @ e1, fused summed = e0 + e1 + e2
    spmm_csr_kernel<false, true><<<spmm_blocks, TPB>>>(
        (const float4*)e1, e2, nullptr, (const float4*)e0,
        (const float4*)e1, summed);
}